// round 1
// baseline (speedup 1.0000x reference)
#include <cuda_runtime.h>
#include <math.h>

#define N 448
#define NP (N*N)
#define NROT 21
#define NSAD_BLK 16
#define PI_D 3.14159265358979323846

// ---------------- device global scratch (no allocations allowed) ----------------
__device__ float  g_A[NROT*NP];
__device__ float  g_B[NROT*NP];
__device__ float  g_rot[NROT*NP];
__device__ float  g_kx[NROT*NP];     // shear-x kernel tables: [rot][y][u]
__device__ float  g_ky[NROT*NP];     // shear-y kernel tables: [rot][x][u]
__device__ float  g_fk[2*NP];        // final rotation tables: fkx, fky
__device__ float  g_t4[4*N];         // final translation kernels: txr, txi, tyr, tyi
__device__ double g_partial[NROT*NSAD_BLK*25];
__device__ float  g_sad[525];
__device__ float  g_res[4];
__device__ float  g_w1[NP], g_w2[NP], g_w3[NP], g_w4[NP];

// ---------------- circulant kernel values (periodic sinc, fftfreq convention) ----------------
// Cr_s(u) = sin(pi*v)*cos(pi*v/N)/(N*sin(pi*v/N)), v = u - s   (real part)
// Ci_s(u) = -sin(pi*v)/N                                        (imag part)
__device__ __forceinline__ float cr_val(double v) {
    double w  = v - 448.0 * rint(v * (1.0/448.0));  // reduce mod N (kernel is N-periodic)
    double nf = rint(w);
    double f  = w - nf;
    int    n  = (int)nf;
    float sf = sinpif((float)f);
    if (n & 1) sf = -sf;                            // sin(pi*w) = (-1)^n sin(pi*f)
    float wf = (float)w;
    if (fabsf(wf) < 1e-6f) return 1.0f;             // removable singularity -> delta
    float arg = wf * (1.0f/448.0f);                 // in [-0.5, 0.5]
    return sf * cospif(arg) / (448.0f * sinpif(arg));
}
__device__ __forceinline__ float ci_val(double v) {
    double w  = v - 448.0 * rint(v * (1.0/448.0));
    double nf = rint(w);
    double f  = w - nf;
    int    n  = (int)nf;
    float sf = sinpif((float)f);
    if (n & 1) sf = -sf;
    return -sf * (1.0f/448.0f);
}

// ---------------- build per-rotation shear tables ----------------
// type 0: shear-x table, row index = y, shift = a*(y - 223.5), a = -tan(th/2)
// type 1: shear-y table, row index = x, shift = b*(x - 223.5), b = sin(th)
__global__ void build_tables() {
    __shared__ double sh_s;
    int r = blockIdx.x, kk = blockIdx.y, type = blockIdx.z;
    if (threadIdx.x == 0) {
        double th = (double)(kk - 10) * (PI_D / 180.0);
        double c  = (type == 0) ? -tan(th * 0.5) : sin(th);
        sh_s = c * ((double)r - 223.5);
    }
    __syncthreads();
    int u = threadIdx.x;
    float* dst = (type == 0) ? g_kx : g_ky;
    dst[(size_t)kk*NP + (size_t)r*N + u] = cr_val((double)u - sh_s);
}

__global__ void build_final_rot() {
    __shared__ double sh_s;
    int r = blockIdx.x, type = blockIdx.y;
    if (threadIdx.x == 0) {
        double th = -(double)g_res[2];
        double c  = (type == 0) ? -tan(th * 0.5) : sin(th);
        sh_s = c * ((double)r - 223.5);
    }
    __syncthreads();
    g_fk[(size_t)type*NP + (size_t)r*N + threadIdx.x] = cr_val((double)threadIdx.x - sh_s);
}

__global__ void build_trans() {
    int u = threadIdx.x;
    double sx = -(double)g_res[0];
    double sy = -(double)g_res[1];
    g_t4[u      ] = cr_val((double)u - sx);
    g_t4[N   + u] = ci_val((double)u - sx);
    g_t4[2*N + u] = cr_val((double)u - sy);
    g_t4[3*N + u] = ci_val((double)u - sy);
}

// ---------------- row-wise circular correlation (one block per (row,image)) ----------------
// out[b][y][x] = sum_{x'} in[b][y][x'] * tab[b][y][(x - x') mod N]
__global__ void shear_rows(const float* __restrict__ in, int inImgStride,
                           float* __restrict__ out,
                           const float* __restrict__ tab, int tabImgStride, int tabRowStride)
{
    __shared__ __align__(16) float s_in[N];
    __shared__ float s_k[2*N];
    int y = blockIdx.x, b = blockIdx.y, t = threadIdx.x;
    const float* ip = in  + (size_t)b*inImgStride  + (size_t)y*N;
    const float* tp = tab + (size_t)b*tabImgStride + (size_t)y*tabRowStride;
    s_in[t] = ip[t];
    float kv = tp[(t + 1) % N];   // s_k[j] holds kernel at diff d = j-447 -> index (j+1) mod N
    s_k[t]     = kv;
    s_k[t + N] = kv;
    __syncthreads();

    const float4* in4 = (const float4*)s_in;
    float acc0 = 0.f, acc1 = 0.f;
    int base = 447 + t;
    #pragma unroll 8
    for (int q = 0; q < N/4; ++q) {
        float4 v = in4[q];
        int xp = q << 2;
        acc0 = fmaf(v.x, s_k[base - xp    ], acc0);
        acc1 = fmaf(v.y, s_k[base - xp - 1], acc1);
        acc0 = fmaf(v.z, s_k[base - xp - 2], acc0);
        acc1 = fmaf(v.w, s_k[base - xp - 3], acc1);
    }
    out[(size_t)b*NP + (size_t)y*N + t] = acc0 + acc1;
}

// ---------------- batched 448x448 transpose ----------------
__global__ void transpose_b(const float* __restrict__ in, float* __restrict__ out) {
    __shared__ float tile[32][33];
    int b = blockIdx.z;
    int x  = blockIdx.x*32 + threadIdx.x;
    int y0 = blockIdx.y*32 + threadIdx.y;
    const float* ip = in + (size_t)b*NP;
    #pragma unroll
    for (int i = 0; i < 32; i += 8)
        tile[threadIdx.y + i][threadIdx.x] = ip[(size_t)(y0 + i)*N + x];
    __syncthreads();
    int x2 = blockIdx.y*32 + threadIdx.x;
    int y2 = blockIdx.x*32 + threadIdx.y;
    float* op = out + (size_t)b*NP;
    #pragma unroll
    for (int i = 0; i < 32; i += 8)
        op[(size_t)(y2 + i)*N + x2] = tile[threadIdx.x][threadIdx.y + i];
}

// ---------------- SAD over 403x403 crop for 25 integer shifts, per rotation ----------------
__global__ void sad_partial(const float* __restrict__ img1) {
    int blk = blockIdx.x, k = blockIdx.y;
    const float* rot = g_rot + (size_t)k*NP;
    float acc[25];
    #pragma unroll
    for (int q = 0; q < 25; ++q) acc[q] = 0.f;

    int y0 = blk * 26;
    int y1 = (y0 + 26 < 403) ? (y0 + 26) : 403;
    for (int y = y0; y < y1; ++y) {
        const float* r1    = img1 + (size_t)(y + 22)*N + 22;
        const float* rbase = rot  + (size_t)(y + 22)*N + 22;
        for (int x = threadIdx.x; x < 403; x += 256) {
            float v1 = r1[x];
            #pragma unroll
            for (int j = 0; j < 5; ++j) {            // sy = j-2
                const float* rr = rbase + x - (j - 2)*N;
                #pragma unroll
                for (int i = 0; i < 5; ++i)          // sx = i-2
                    acc[i*5 + j] += fabsf(v1 - rr[2 - i]);
            }
        }
    }

    __shared__ double sbin[8][25];
    int w = threadIdx.x >> 5, l = threadIdx.x & 31;
    #pragma unroll
    for (int q = 0; q < 25; ++q) {
        double d = (double)acc[q];
        #pragma unroll
        for (int o = 16; o > 0; o >>= 1)
            d += __shfl_down_sync(0xffffffffu, d, o);
        if (l == 0) sbin[w][q] = d;
    }
    __syncthreads();
    if (threadIdx.x < 25) {
        double s = 0.0;
        #pragma unroll
        for (int w2 = 0; w2 < 8; ++w2) s += sbin[w2][threadIdx.x];
        g_partial[((size_t)k*NSAD_BLK + blk)*25 + threadIdx.x] = s;
    }
}

__global__ void sad_reduce() {
    int v = threadIdx.x;
    if (v >= 525) return;
    int k = v % 21, ij = v / 21;
    double s = 0.0;
    for (int b = 0; b < NSAD_BLK; ++b)
        s += g_partial[((size_t)k*NSAD_BLK + b)*25 + ij];
    g_sad[ij*21 + k] = (float)(s * (1.0 / 162409.0));   // /(403*403)
}

// ---------------- argmin + parabolic refinement ----------------
__global__ void argmin_refine(float* d_out, int off) {
    if (threadIdx.x != 0) return;
    float mn = g_sad[0]; int idx = 0;
    for (int v = 1; v < 525; ++v) {
        float s = g_sad[v];
        if (s < mn) { mn = s; idx = v; }
    }
    int i = idx / 105, j = (idx / 21) % 5, k = idx % 21;

    float x0 = g_sad[((i+4)%5)*105 + j*21 + k];
    float x2 = g_sad[((i+1)%5)*105 + j*21 + k];
    float y0v = g_sad[i*105 + ((j+4)%5)*21 + k];
    float y2v = g_sad[i*105 + ((j+1)%5)*21 + k];
    float r0 = g_sad[i*105 + j*21 + (k+20)%21];
    float r2 = g_sad[i*105 + j*21 + (k+1)%21];
    float p1 = mn;

    auto pd = [](float a0, float a1, float a2) {
        float a = 0.5f*(a0 + a2) - a1;
        float b = 0.5f*(a2 - a0);
        return -b / (2.0f * a);
    };
    float sx  = (float)(i - 2) + pd(x0, p1, x2);
    float sy  = (float)(j - 2) + pd(y0v, p1, y2v);
    float rot = ((float)(k - 10) + pd(r0, p1, r2)) * (float)(PI_D / 180.0);

    g_res[0] = sx; g_res[1] = sy; g_res[2] = rot;
    if (off >= 3) { d_out[0] = sx; d_out[1] = sy; d_out[2] = rot; }
}

// ---------------- final combine: out[y][x] = pr^T - pi^T ----------------
__global__ void final_combine(const float* __restrict__ pr, const float* __restrict__ pi,
                              float* __restrict__ out) {
    __shared__ float t1[32][33], t2[32][33];
    int x  = blockIdx.x*32 + threadIdx.x;
    int y0 = blockIdx.y*32 + threadIdx.y;
    #pragma unroll
    for (int i = 0; i < 32; i += 8) {
        t1[threadIdx.y + i][threadIdx.x] = pr[(size_t)(y0 + i)*N + x];
        t2[threadIdx.y + i][threadIdx.x] = pi[(size_t)(y0 + i)*N + x];
    }
    __syncthreads();
    int x2 = blockIdx.y*32 + threadIdx.x;
    int y2 = blockIdx.x*32 + threadIdx.y;
    #pragma unroll
    for (int i = 0; i < 32; i += 8)
        out[(size_t)(y2 + i)*N + x2] =
            t1[threadIdx.x][threadIdx.y + i] - t2[threadIdx.x][threadIdx.y + i];
}

// ---------------- host launch ----------------
extern "C" void kernel_launch(void* const* d_in, const int* in_sizes, int n_in,
                              void* d_out, int out_size) {
    const float* img1 = (const float*)d_in[0];
    const float* img2 = (const float*)d_in[1];
    float* out = (float*)d_out;
    int off = out_size - NP;
    if (off < 0) off = 0;

    float *pA, *pB, *pRot, *pKx, *pKy, *pFk, *pT4, *pW1, *pW2, *pW3, *pW4;
    cudaGetSymbolAddress((void**)&pA,   g_A);
    cudaGetSymbolAddress((void**)&pB,   g_B);
    cudaGetSymbolAddress((void**)&pRot, g_rot);
    cudaGetSymbolAddress((void**)&pKx,  g_kx);
    cudaGetSymbolAddress((void**)&pKy,  g_ky);
    cudaGetSymbolAddress((void**)&pFk,  g_fk);
    cudaGetSymbolAddress((void**)&pT4,  g_t4);
    cudaGetSymbolAddress((void**)&pW1,  g_w1);
    cudaGetSymbolAddress((void**)&pW2,  g_w2);
    cudaGetSymbolAddress((void**)&pW3,  g_w3);
    cudaGetSymbolAddress((void**)&pW4,  g_w4);

    dim3 tb(32, 8);
    dim3 tg(14, 14, NROT);
    dim3 tg1(14, 14, 1);

    // 21 rotations: shearX -> shearY -> shearX (shearY done transposed)
    build_tables<<<dim3(N, NROT, 2), N>>>();
    shear_rows<<<dim3(N, NROT), N>>>(img2, 0,  pA,   pKx, NP, N);
    transpose_b<<<tg, tb>>>(pA, pB);
    shear_rows<<<dim3(N, NROT), N>>>(pB,  NP,  pA,   pKy, NP, N);
    transpose_b<<<tg, tb>>>(pA, pB);
    shear_rows<<<dim3(N, NROT), N>>>(pB,  NP,  pRot, pKx, NP, N);

    // SAD over 525 (sx, sy, rot) combos (integer shifts = index offsets)
    sad_partial<<<dim3(NSAD_BLK, NROT), 256>>>(img1);
    sad_reduce<<<1, 544>>>();
    argmin_refine<<<1, 32>>>(out, off);

    // final warp: rotate(img2, -rot_sub) then fractional translate(-sx_sub, -sy_sub)
    build_final_rot<<<dim3(N, 2), N>>>();
    build_trans<<<1, N>>>();
    shear_rows<<<dim3(N, 1), N>>>(img2, 0, pW1, pFk,      0, N);
    transpose_b<<<tg1, tb>>>(pW1, pW2);
    shear_rows<<<dim3(N, 1), N>>>(pW2, 0, pW1, pFk + NP,  0, N);
    transpose_b<<<tg1, tb>>>(pW1, pW2);
    shear_rows<<<dim3(N, 1), N>>>(pW2, 0, pW1, pFk,       0, N);   // rotated image in pW1

    // translation: Re part = (Cr_y)(Cr_x)g, Im part correction = (Ci_y)(Ci_x)g
    shear_rows<<<dim3(N, 1), N>>>(pW1, 0, pW2, pT4,        0, 0);  // Br g
    transpose_b<<<tg1, tb>>>(pW2, pW3);
    shear_rows<<<dim3(N, 1), N>>>(pW3, 0, pW4, pT4 + 2*N,  0, 0);  // (Ar Br g)^T
    shear_rows<<<dim3(N, 1), N>>>(pW1, 0, pW2, pT4 + N,    0, 0);  // Bi g
    transpose_b<<<tg1, tb>>>(pW2, pW3);
    shear_rows<<<dim3(N, 1), N>>>(pW3, 0, pW2, pT4 + 3*N,  0, 0);  // (Ai Bi g)^T

    final_combine<<<tg1, tb>>>(pW4, pW2, out + off);
}

// round 2
// speedup vs baseline: 2.8345x; 2.8345x over previous
#include <cuda_runtime.h>
#include <math.h>

#define N 448
#define NP (N*N)
#define NROT 21
#define NSAD_BLK 16
#define PI_D 3.14159265358979323846

// ---------------- device global scratch (no allocations allowed) ----------------
__device__ __align__(16) float  g_A[NROT*NP];
__device__ __align__(16) float  g_B[NROT*NP];
__device__ __align__(16) float  g_rot[NROT*NP];
__device__ __align__(16) float  g_kx[NROT*NP];     // shear-x kernel tables: [rot][y][d]
__device__ __align__(16) float  g_ky[NROT*NP];     // shear-y kernel tables: [rot][x][d]
__device__ __align__(16) float  g_fk[2*NP];        // final rotation tables
__device__ __align__(16) float  g_t4[4*N];         // final translation kernels
__device__ double g_partial[NROT*NSAD_BLK*25];
__device__ float  g_sad[525];
__device__ float  g_res[4];
__device__ __align__(16) float  g_w1[NP], g_w2[NP], g_w3[NP], g_w4[NP];

// ---------------- circulant kernel values ----------------
// k[d] = Cr(d - s) where Cr(v) = sin(pi v) cos(pi v/N) / (N sin(pi v/N)), N-periodic.
// With s = si + sf (si integer, sf in [0,1)), m = (d - si) mod N, w = centered(m - sf):
//   sin(pi*w) = -(-1)^m * sin(pi*sf)          (mod-N shift is even, harmless)
__device__ __forceinline__ float cr_from(int m, float sf, float S) {
    float w0 = (float)m - sf;                       // in (-1, 447]
    float w  = (w0 > 224.0f) ? (w0 - 448.0f) : w0;  // |w| <= 224
    if (fabsf(w) < 1e-7f) return 1.0f;              // removable singularity -> delta
    float num = (m & 1) ? S : -S;                   // -(-1)^m * sin(pi*sf)
    float arg = w * (1.0f/448.0f);
    return num * cospif(arg) / (448.0f * sinpif(arg));
}
__device__ __forceinline__ float ci_from(int m, float sf, float S) {
    return ((m & 1) ? -S : S) * (1.0f/448.0f);      // (-1)^m * sin(pi*sf)/N
}
__device__ __forceinline__ int mod_si(double si) {
    int sii = (int)si;
    return ((sii % 448) + 448) % 448;
}

// ---------------- build per-rotation shear tables ----------------
__global__ void build_tables() {
    __shared__ float sh_sf, sh_S; __shared__ int sh_m0;
    int r = blockIdx.x, kk = blockIdx.y, type = blockIdx.z;
    if (threadIdx.x == 0) {
        double th = (double)(kk - 10) * (PI_D / 180.0);
        double c  = (type == 0) ? -tan(th * 0.5) : sin(th);
        double s  = c * ((double)r - 223.5);
        double si = floor(s);
        float sf  = (float)(s - si);
        sh_sf = sf; sh_S = sinpif(sf); sh_m0 = mod_si(si);
    }
    __syncthreads();
    int u = threadIdx.x;
    int m = u - sh_m0; if (m < 0) m += 448;
    float* dst = (type == 0) ? g_kx : g_ky;
    dst[(size_t)kk*NP + (size_t)r*N + u] = cr_from(m, sh_sf, sh_S);
}

__global__ void build_final_rot() {
    __shared__ float sh_sf, sh_S; __shared__ int sh_m0;
    int r = blockIdx.x, type = blockIdx.y;
    if (threadIdx.x == 0) {
        double th = -(double)g_res[2];
        double c  = (type == 0) ? -tan(th * 0.5) : sin(th);
        double s  = c * ((double)r - 223.5);
        double si = floor(s);
        float sf  = (float)(s - si);
        sh_sf = sf; sh_S = sinpif(sf); sh_m0 = mod_si(si);
    }
    __syncthreads();
    int u = threadIdx.x;
    int m = u - sh_m0; if (m < 0) m += 448;
    g_fk[(size_t)type*NP + (size_t)r*N + u] = cr_from(m, sh_sf, sh_S);
}

__global__ void build_trans() {
    __shared__ float sfx, Sx, sfy, Sy; __shared__ int m0x, m0y;
    if (threadIdx.x == 0) {
        double sx = -(double)g_res[0];
        double sy = -(double)g_res[1];
        double six = floor(sx), siy = floor(sy);
        sfx = (float)(sx - six); Sx = sinpif(sfx); m0x = mod_si(six);
        sfy = (float)(sy - siy); Sy = sinpif(sfy); m0y = mod_si(siy);
    }
    __syncthreads();
    int u = threadIdx.x;
    int mx = u - m0x; if (mx < 0) mx += 448;
    int my = u - m0y; if (my < 0) my += 448;
    g_t4[u      ] = cr_from(mx, sfx, Sx);
    g_t4[N   + u] = ci_from(mx, sfx, Sx);
    g_t4[2*N + u] = cr_from(my, sfy, Sy);
    g_t4[3*N + u] = ci_from(my, sfy, Sy);
}

// ---------------- row-wise circular correlation, register-blocked ----------------
// out[b][y][x] = sum_d in[b][y][(x-d) mod N] * tab[b][y][d]
// Block = 448 threads = 4 rows x 112 threads; each thread computes 4 outputs.
__global__ void __launch_bounds__(448) shear_rows(
    const float* __restrict__ in, int inImgStride,
    float* __restrict__ out,
    const float* __restrict__ tab, int tabImgStride, int tabRowStride)
{
    __shared__ __align__(16) float s_in2[4*896];   // each row duplicated (circular)
    __shared__ __align__(16) float s_k[4*448];
    int b = blockIdx.y;
    int y0 = blockIdx.x * 4;
    int t = threadIdx.x;

    // load kernel rows: 448 float4s
    {
        int row = t / 112, c4 = t % 112;
        const float* tp = tab + (size_t)b*tabImgStride + (size_t)(y0 + row)*tabRowStride;
        ((float4*)s_k)[t] = ((const float4*)tp)[c4];
    }
    // load input rows duplicated: 896 float4s (2 per thread)
    #pragma unroll
    for (int p = t; p < 896; p += 448) {
        int row = p / 224, c4 = p % 224;
        int cc = (c4 >= 112) ? (c4 - 112) : c4;
        const float* ip = in + (size_t)b*inImgStride + (size_t)(y0 + row)*N;
        ((float4*)s_in2)[p] = ((const float4*)ip)[cc];
    }
    __syncthreads();

    int lr = t / 112, li = t % 112;
    const float4* in4 = (const float4*)(s_in2 + lr*896);
    const float4* k4  = (const float4*)(s_k  + lr*448);
    int pbase = li + 112;          // float4 index of s_in2[x0 + 448]

    float ax = 0.f, ay = 0.f, az = 0.f, aw = 0.f;
    float4 bb = in4[pbase];        // in[x0+448 .. x0+451] == in[x0..x0+3]
    #pragma unroll 4
    for (int q = 0; q < 112; ++q) {
        float4 kv = k4[q];                 // broadcast within row group
        float4 aa = in4[pbase - q - 1];    // in[j-4 .. j-1], j = x0+448-4q
        // out[x0+i] += in[j+i-dd]*k[4q+dd]
        ax = fmaf(bb.x, kv.x, ax); ax = fmaf(aa.w, kv.y, ax); ax = fmaf(aa.z, kv.z, ax); ax = fmaf(aa.y, kv.w, ax);
        ay = fmaf(bb.y, kv.x, ay); ay = fmaf(bb.x, kv.y, ay); ay = fmaf(aa.w, kv.z, ay); ay = fmaf(aa.z, kv.w, ay);
        az = fmaf(bb.z, kv.x, az); az = fmaf(bb.y, kv.y, az); az = fmaf(bb.x, kv.z, az); az = fmaf(aa.w, kv.w, az);
        aw = fmaf(bb.w, kv.x, aw); aw = fmaf(bb.z, kv.y, aw); aw = fmaf(bb.y, kv.z, aw); aw = fmaf(bb.x, kv.w, aw);
        bb = aa;
    }
    float4 o; o.x = ax; o.y = ay; o.z = az; o.w = aw;
    ((float4*)(out + (size_t)b*NP + (size_t)(y0 + lr)*N))[li] = o;
}

// ---------------- batched 448x448 transpose ----------------
__global__ void transpose_b(const float* __restrict__ in, float* __restrict__ out) {
    __shared__ float tile[32][33];
    int b = blockIdx.z;
    int x  = blockIdx.x*32 + threadIdx.x;
    int y0 = blockIdx.y*32 + threadIdx.y;
    const float* ip = in + (size_t)b*NP;
    #pragma unroll
    for (int i = 0; i < 32; i += 8)
        tile[threadIdx.y + i][threadIdx.x] = ip[(size_t)(y0 + i)*N + x];
    __syncthreads();
    int x2 = blockIdx.y*32 + threadIdx.x;
    int y2 = blockIdx.x*32 + threadIdx.y;
    float* op = out + (size_t)b*NP;
    #pragma unroll
    for (int i = 0; i < 32; i += 8)
        op[(size_t)(y2 + i)*N + x2] = tile[threadIdx.x][threadIdx.y + i];
}

// ---------------- SAD over 403x403 crop for 25 integer shifts, per rotation ----------------
__global__ void sad_partial(const float* __restrict__ img1) {
    int blk = blockIdx.x, k = blockIdx.y;
    const float* rot = g_rot + (size_t)k*NP;
    float acc[25];
    #pragma unroll
    for (int q = 0; q < 25; ++q) acc[q] = 0.f;

    int y0 = blk * 26;
    int y1 = (y0 + 26 < 403) ? (y0 + 26) : 403;
    for (int y = y0; y < y1; ++y) {
        const float* r1    = img1 + (size_t)(y + 22)*N + 22;
        const float* rbase = rot  + (size_t)(y + 22)*N + 22;
        for (int x = threadIdx.x; x < 403; x += 256) {
            float v1 = r1[x];
            #pragma unroll
            for (int j = 0; j < 5; ++j) {
                const float* rr = rbase + x - (j - 2)*N;
                #pragma unroll
                for (int i = 0; i < 5; ++i)
                    acc[i*5 + j] += fabsf(v1 - rr[2 - i]);
            }
        }
    }

    __shared__ double sbin[8][25];
    int w = threadIdx.x >> 5, l = threadIdx.x & 31;
    #pragma unroll
    for (int q = 0; q < 25; ++q) {
        double d = (double)acc[q];
        #pragma unroll
        for (int o = 16; o > 0; o >>= 1)
            d += __shfl_down_sync(0xffffffffu, d, o);
        if (l == 0) sbin[w][q] = d;
    }
    __syncthreads();
    if (threadIdx.x < 25) {
        double s = 0.0;
        #pragma unroll
        for (int w2 = 0; w2 < 8; ++w2) s += sbin[w2][threadIdx.x];
        g_partial[((size_t)k*NSAD_BLK + blk)*25 + threadIdx.x] = s;
    }
}

__global__ void sad_reduce() {
    int v = threadIdx.x;
    if (v >= 525) return;
    int k = v % 21, ij = v / 21;
    double s = 0.0;
    for (int b = 0; b < NSAD_BLK; ++b)
        s += g_partial[((size_t)k*NSAD_BLK + b)*25 + ij];
    g_sad[ij*21 + k] = (float)(s * (1.0 / 162409.0));
}

// ---------------- argmin + parabolic refinement ----------------
__global__ void argmin_refine(float* d_out, int off) {
    if (threadIdx.x != 0) return;
    float mn = g_sad[0]; int idx = 0;
    for (int v = 1; v < 525; ++v) {
        float s = g_sad[v];
        if (s < mn) { mn = s; idx = v; }
    }
    int i = idx / 105, j = (idx / 21) % 5, k = idx % 21;

    float x0 = g_sad[((i+4)%5)*105 + j*21 + k];
    float x2 = g_sad[((i+1)%5)*105 + j*21 + k];
    float y0v = g_sad[i*105 + ((j+4)%5)*21 + k];
    float y2v = g_sad[i*105 + ((j+1)%5)*21 + k];
    float r0 = g_sad[i*105 + j*21 + (k+20)%21];
    float r2 = g_sad[i*105 + j*21 + (k+1)%21];
    float p1 = mn;

    auto pd = [](float a0, float a1, float a2) {
        float a = 0.5f*(a0 + a2) - a1;
        float b = 0.5f*(a2 - a0);
        return -b / (2.0f * a);
    };
    float sx  = (float)(i - 2) + pd(x0, p1, x2);
    float sy  = (float)(j - 2) + pd(y0v, p1, y2v);
    float rot = ((float)(k - 10) + pd(r0, p1, r2)) * (float)(PI_D / 180.0);

    g_res[0] = sx; g_res[1] = sy; g_res[2] = rot;
    if (off >= 3) { d_out[0] = sx; d_out[1] = sy; d_out[2] = rot; }
}

// ---------------- final combine: out[y][x] = pr^T - pi^T ----------------
__global__ void final_combine(const float* __restrict__ pr, const float* __restrict__ pi,
                              float* __restrict__ out) {
    __shared__ float t1[32][33], t2[32][33];
    int x  = blockIdx.x*32 + threadIdx.x;
    int y0 = blockIdx.y*32 + threadIdx.y;
    #pragma unroll
    for (int i = 0; i < 32; i += 8) {
        t1[threadIdx.y + i][threadIdx.x] = pr[(size_t)(y0 + i)*N + x];
        t2[threadIdx.y + i][threadIdx.x] = pi[(size_t)(y0 + i)*N + x];
    }
    __syncthreads();
    int x2 = blockIdx.y*32 + threadIdx.x;
    int y2 = blockIdx.x*32 + threadIdx.y;
    #pragma unroll
    for (int i = 0; i < 32; i += 8)
        out[(size_t)(y2 + i)*N + x2] =
            t1[threadIdx.x][threadIdx.y + i] - t2[threadIdx.x][threadIdx.y + i];
}

// ---------------- host launch ----------------
extern "C" void kernel_launch(void* const* d_in, const int* in_sizes, int n_in,
                              void* d_out, int out_size) {
    const float* img1 = (const float*)d_in[0];
    const float* img2 = (const float*)d_in[1];
    float* out = (float*)d_out;
    int off = out_size - NP;
    if (off < 0) off = 0;

    float *pA, *pB, *pRot, *pKx, *pKy, *pFk, *pT4, *pW1, *pW2, *pW3, *pW4;
    cudaGetSymbolAddress((void**)&pA,   g_A);
    cudaGetSymbolAddress((void**)&pB,   g_B);
    cudaGetSymbolAddress((void**)&pRot, g_rot);
    cudaGetSymbolAddress((void**)&pKx,  g_kx);
    cudaGetSymbolAddress((void**)&pKy,  g_ky);
    cudaGetSymbolAddress((void**)&pFk,  g_fk);
    cudaGetSymbolAddress((void**)&pT4,  g_t4);
    cudaGetSymbolAddress((void**)&pW1,  g_w1);
    cudaGetSymbolAddress((void**)&pW2,  g_w2);
    cudaGetSymbolAddress((void**)&pW3,  g_w3);
    cudaGetSymbolAddress((void**)&pW4,  g_w4);

    dim3 tb(32, 8);
    dim3 tg(14, 14, NROT);
    dim3 tg1(14, 14, 1);
    dim3 sg(112, NROT);
    dim3 sg1(112, 1);

    // 21 rotations: shearX -> shearY -> shearX (shearY done transposed)
    build_tables<<<dim3(N, NROT, 2), N>>>();
    shear_rows<<<sg, 448>>>(img2, 0,  pA,   pKx, NP, N);
    transpose_b<<<tg, tb>>>(pA, pB);
    shear_rows<<<sg, 448>>>(pB,  NP,  pA,   pKy, NP, N);
    transpose_b<<<tg, tb>>>(pA, pB);
    shear_rows<<<sg, 448>>>(pB,  NP,  pRot, pKx, NP, N);

    // SAD over 525 (sx, sy, rot) combos (integer shifts = index offsets)
    sad_partial<<<dim3(NSAD_BLK, NROT), 256>>>(img1);
    sad_reduce<<<1, 544>>>();
    argmin_refine<<<1, 32>>>(out, off);

    // final warp: rotate(img2, -rot_sub) then fractional translate(-sx_sub, -sy_sub)
    build_final_rot<<<dim3(N, 2), N>>>();
    build_trans<<<1, N>>>();
    shear_rows<<<sg1, 448>>>(img2, 0, pW1, pFk,      0, N);
    transpose_b<<<tg1, tb>>>(pW1, pW2);
    shear_rows<<<sg1, 448>>>(pW2, 0, pW1, pFk + NP,  0, N);
    transpose_b<<<tg1, tb>>>(pW1, pW2);
    shear_rows<<<sg1, 448>>>(pW2, 0, pW1, pFk,       0, N);   // rotated image in pW1

    // translation: Re = (Cr_y)(Cr_x)g - (Ci_y)(Ci_x)g
    shear_rows<<<sg1, 448>>>(pW1, 0, pW2, pT4,        0, 0);  // Br g
    transpose_b<<<tg1, tb>>>(pW2, pW3);
    shear_rows<<<sg1, 448>>>(pW3, 0, pW4, pT4 + 2*N,  0, 0);  // (Ar Br g)^T
    shear_rows<<<sg1, 448>>>(pW1, 0, pW2, pT4 + N,    0, 0);  // Bi g
    transpose_b<<<tg1, tb>>>(pW2, pW3);
    shear_rows<<<sg1, 448>>>(pW3, 0, pW2, pT4 + 3*N,  0, 0);  // (Ai Bi g)^T

    final_combine<<<tg1, tb>>>(pW4, pW2, out + off);
}